// round 4
// baseline (speedup 1.0000x reference)
#include <cuda_runtime.h>
#include <cuda_fp16.h>
#include <cstdint>

// ---------------------------------------------------------------------------
// TableGNN: encoder MLP -> GAT(4 heads x 32ch) -> ReLU -> GAT -> two head MLPs
// N=50000, E=1.6M (+N self loops), D=128.
// Round 4: edge softmax weights precomputed edge-parallel (fp32) so the
// per-node gather loop has no exp and no random scalar chase; fp16 message
// tensor; attention scores fused into GAT GEMM epilogue; CSR gather.
// ---------------------------------------------------------------------------

#define MAXN 50176
#define MAXE 1700000

__device__ float  d_t   [MAXN * 128];
__device__ float  d_h   [MAXN * 128];
__device__ __half d_gh  [MAXN * 128];
__device__ float  d_as  [MAXN * 4];
__device__ float  d_ad  [MAXN * 4];
__device__ float  d_wcat[128 * 128];
__device__ float  d_bcat[128];
__device__ int    d_off [MAXN + 1];
__device__ int    d_cur [MAXN];        // doubles as histogram counter
__device__ int    d_csrs[MAXE];
__device__ int    d_csrd[MAXE];
__device__ float4 d_pw  [MAXE];        // per-edge softmax numerators (4 heads)
__device__ int    d_bsum[64];
__device__ int    d_is64;

// ---------------------------------------------------------------------------
// detect whether edge_index is int64 (odd 32-bit words all zero) or int32
__global__ void detect_kernel(const int* __restrict__ ei)
{
    if (threadIdx.x == 0 && blockIdx.x == 0) {
        int f = 1;
        #pragma unroll
        for (int i = 1; i < 64; i += 2)
            if (ei[i] != 0) f = 0;
        d_is64 = f;
    }
}

__device__ __forceinline__ void load_edge(const void* ei, int E, int N, int i,
                                          int& s, int& d)
{
    if (i < E) {
        if (d_is64) {
            const long long* p = (const long long*)ei;
            s = (int)__ldg(p + i);
            d = (int)__ldg(p + E + i);
        } else {
            const int* p = (const int*)ei;
            s = __ldg(p + i);
            d = __ldg(p + E + i);
        }
    } else {
        s = d = i - E;   // self loop
    }
}

// ---------------------------------------------------------------------------
// CSR build: histogram of dst (incl. self loops)
__global__ void hist_kernel(const void* __restrict__ ei, int E, int N,
                            int* __restrict__ cnt)
{
    int i = blockIdx.x * blockDim.x + threadIdx.x;
    if (i >= E + N) return;
    int s, d;
    load_edge(ei, E, N, i, s, d);
    atomicAdd(&cnt[d], 1);
}

// per-block exclusive scan (1024 elems), block totals to bsum
__global__ void scan1_kernel(const int* __restrict__ cnt,
                             int* __restrict__ off,
                             int* __restrict__ bsum, int N)
{
    __shared__ int sh[1024];
    int i = blockIdx.x * 1024 + threadIdx.x;
    int v = (i < N) ? cnt[i] : 0;
    sh[threadIdx.x] = v;
    __syncthreads();
    for (int s = 1; s < 1024; s <<= 1) {
        int t = (threadIdx.x >= s) ? sh[threadIdx.x - s] : 0;
        __syncthreads();
        sh[threadIdx.x] += t;
        __syncthreads();
    }
    if (i < N) off[i] = sh[threadIdx.x] - v;
    if (threadIdx.x == 1023) bsum[blockIdx.x] = sh[1023];
}

// exclusive scan of block totals (nb <= 64), one 64-thread block
__global__ void scan2_kernel(int* __restrict__ bsum, int nb)
{
    __shared__ int sh[64];
    int v = (threadIdx.x < nb) ? bsum[threadIdx.x] : 0;
    sh[threadIdx.x] = v;
    __syncthreads();
    #pragma unroll
    for (int s = 1; s < 64; s <<= 1) {
        int t = (threadIdx.x >= s) ? sh[threadIdx.x - s] : 0;
        __syncthreads();
        sh[threadIdx.x] += t;
        __syncthreads();
    }
    if (threadIdx.x < nb) bsum[threadIdx.x] = sh[threadIdx.x] - v;
}

// adds block prefix, writes final off AND the scatter cursor copy
__global__ void scan3_kernel(int* __restrict__ off, const int* __restrict__ bsum,
                             int* __restrict__ cur, int N, int total)
{
    int i = blockIdx.x * blockDim.x + threadIdx.x;
    if (i < N) {
        int v = off[i] + bsum[i >> 10];
        off[i] = v;
        cur[i] = v;
    }
    if (i == 0) off[N] = total;
}

// scatter src AND dst ids into CSR order
__global__ void scatter_kernel(const void* __restrict__ ei, int E, int N,
                               int* __restrict__ cur,
                               int* __restrict__ csrs,
                               int* __restrict__ csrd)
{
    int i = blockIdx.x * blockDim.x + threadIdx.x;
    if (i >= E + N) return;
    int s, d;
    load_edge(ei, E, N, i, s, d);
    int pos = atomicAdd(&cur[d], 1);
    csrs[pos] = s;
    csrd[pos] = d;
}

// ---------------------------------------------------------------------------
// t[n][c] = relu(b1[c] + sum_k x[n][k] * w1[k][c]), K=8
__global__ void encoder1_kernel(const float* __restrict__ x,
                                const float* __restrict__ w1,
                                const float* __restrict__ b1,
                                float* __restrict__ t, int N)
{
    int idx = blockIdx.x * blockDim.x + threadIdx.x;
    if (idx >= N * 128) return;
    int n = idx >> 7, c = idx & 127;
    float s = b1[c];
    #pragma unroll
    for (int k = 0; k < 8; k++)
        s += x[n * 8 + k] * w1[k * 128 + c];
    t[idx] = fmaxf(s, 0.f);
}

// ---------------------------------------------------------------------------
// fp32 GEMM: C[N,128] = act(A[N,128] @ W[128,128] + bias)
// 128x128 block tile, BK=16, 256 threads, 8x8 micro-tile, As transposed.
__launch_bounds__(256)
__global__ void gemm128_kernel(const float* __restrict__ A,
                               const float* __restrict__ W,
                               const float* __restrict__ bias,
                               float* __restrict__ C,
                               int N, int act)
{
    __shared__ float As[16][128];   // [k][m]
    __shared__ float Ws[16][128];   // [k][n]
    const int tid = threadIdx.x;
    const int rowBase = blockIdx.x * 128;
    const int tx = tid & 15, ty = tid >> 4;
    const int r0 = ty * 8, c0 = tx * 8;

    float acc[8][8];
    #pragma unroll
    for (int i = 0; i < 8; i++)
        #pragma unroll
        for (int j = 0; j < 8; j++) acc[i][j] = 0.f;

    const int arow = tid >> 1;
    const int akg  = (tid & 1) * 8;
    const int wk   = (tid * 8) >> 7;
    const int wn   = (tid * 8) & 127;

    for (int kc = 0; kc < 128; kc += 16) {
        float4 a0 = make_float4(0.f, 0.f, 0.f, 0.f);
        float4 a1 = make_float4(0.f, 0.f, 0.f, 0.f);
        if (rowBase + arow < N) {
            const float* ap = A + (size_t)(rowBase + arow) * 128 + kc + akg;
            a0 = *(const float4*)ap;
            a1 = *(const float4*)(ap + 4);
        }
        As[akg + 0][arow] = a0.x; As[akg + 1][arow] = a0.y;
        As[akg + 2][arow] = a0.z; As[akg + 3][arow] = a0.w;
        As[akg + 4][arow] = a1.x; As[akg + 5][arow] = a1.y;
        As[akg + 6][arow] = a1.z; As[akg + 7][arow] = a1.w;

        const float* wp = W + (size_t)(kc + wk) * 128 + wn;
        *(float4*)(&Ws[wk][wn])     = *(const float4*)wp;
        *(float4*)(&Ws[wk][wn + 4]) = *(const float4*)(wp + 4);
        __syncthreads();

        #pragma unroll
        for (int kk = 0; kk < 16; kk++) {
            float4 af0 = *(const float4*)(&As[kk][r0]);
            float4 af1 = *(const float4*)(&As[kk][r0 + 4]);
            float4 wf0 = *(const float4*)(&Ws[kk][c0]);
            float4 wf1 = *(const float4*)(&Ws[kk][c0 + 4]);
            float a[8] = {af0.x, af0.y, af0.z, af0.w, af1.x, af1.y, af1.z, af1.w};
            float w[8] = {wf0.x, wf0.y, wf0.z, wf0.w, wf1.x, wf1.y, wf1.z, wf1.w};
            #pragma unroll
            for (int i = 0; i < 8; i++)
                #pragma unroll
                for (int j = 0; j < 8; j++)
                    acc[i][j] += a[i] * w[j];
        }
        __syncthreads();
    }

    float b[8];
    #pragma unroll
    for (int j = 0; j < 8; j++) b[j] = bias ? bias[c0 + j] : 0.f;

    #pragma unroll
    for (int i = 0; i < 8; i++) {
        int r = rowBase + r0 + i;
        if (r < N) {
            float* cp = C + (size_t)r * 128 + c0;
            #pragma unroll
            for (int j = 0; j < 8; j++) {
                float v = acc[i][j] + b[j];
                if (act) v = fmaxf(v, 0.f);
                cp[j] = v;
            }
        }
    }
}

// ---------------------------------------------------------------------------
// GAT projection GEMM: G = h @ gw (no bias). Epilogue:
//  - writes G as fp16 (message tensor for the gather)
//  - computes a_s[n][h], a_d[n][h] from the fp32 accumulators (shfl reduce)
__launch_bounds__(256)
__global__ void gemm_gat_kernel(const float* __restrict__ A,
                                const float* __restrict__ W,
                                const float* __restrict__ ws,
                                const float* __restrict__ wd,
                                __half* __restrict__ gh,
                                float* __restrict__ a_s,
                                float* __restrict__ a_d,
                                int N)
{
    __shared__ float As[16][128];
    __shared__ float Ws[16][128];
    const int tid = threadIdx.x;
    const int rowBase = blockIdx.x * 128;
    const int tx = tid & 15, ty = tid >> 4;
    const int r0 = ty * 8, c0 = tx * 8;

    float acc[8][8];
    #pragma unroll
    for (int i = 0; i < 8; i++)
        #pragma unroll
        for (int j = 0; j < 8; j++) acc[i][j] = 0.f;

    const int arow = tid >> 1;
    const int akg  = (tid & 1) * 8;
    const int wk   = (tid * 8) >> 7;
    const int wn   = (tid * 8) & 127;

    for (int kc = 0; kc < 128; kc += 16) {
        float4 a0 = make_float4(0.f, 0.f, 0.f, 0.f);
        float4 a1 = make_float4(0.f, 0.f, 0.f, 0.f);
        if (rowBase + arow < N) {
            const float* ap = A + (size_t)(rowBase + arow) * 128 + kc + akg;
            a0 = *(const float4*)ap;
            a1 = *(const float4*)(ap + 4);
        }
        As[akg + 0][arow] = a0.x; As[akg + 1][arow] = a0.y;
        As[akg + 2][arow] = a0.z; As[akg + 3][arow] = a0.w;
        As[akg + 4][arow] = a1.x; As[akg + 5][arow] = a1.y;
        As[akg + 6][arow] = a1.z; As[akg + 7][arow] = a1.w;

        const float* wp = W + (size_t)(kc + wk) * 128 + wn;
        *(float4*)(&Ws[wk][wn])     = *(const float4*)wp;
        *(float4*)(&Ws[wk][wn + 4]) = *(const float4*)(wp + 4);
        __syncthreads();

        #pragma unroll
        for (int kk = 0; kk < 16; kk++) {
            float4 af0 = *(const float4*)(&As[kk][r0]);
            float4 af1 = *(const float4*)(&As[kk][r0 + 4]);
            float4 wf0 = *(const float4*)(&Ws[kk][c0]);
            float4 wf1 = *(const float4*)(&Ws[kk][c0 + 4]);
            float a[8] = {af0.x, af0.y, af0.z, af0.w, af1.x, af1.y, af1.z, af1.w};
            float w[8] = {wf0.x, wf0.y, wf0.z, wf0.w, wf1.x, wf1.y, wf1.z, wf1.w};
            #pragma unroll
            for (int i = 0; i < 8; i++)
                #pragma unroll
                for (int j = 0; j < 8; j++)
                    acc[i][j] += a[i] * w[j];
        }
        __syncthreads();
    }

    // attention-vector slices for this thread's 8 columns
    float wsv[8], wdv[8];
    #pragma unroll
    for (int j = 0; j < 8; j++) {
        wsv[j] = __ldg(ws + c0 + j);
        wdv[j] = __ldg(wd + c0 + j);
    }

    const int head = tx >> 2;   // 8-col group never crosses a 32-ch head

    #pragma unroll
    for (int i = 0; i < 8; i++) {
        int r = rowBase + r0 + i;

        // fp16 message row segment
        if (r < N) {
            __half2 hv[4];
            #pragma unroll
            for (int j = 0; j < 4; j++)
                hv[j] = __floats2half2_rn(acc[i][2 * j], acc[i][2 * j + 1]);
            *(uint4*)(gh + (size_t)r * 128 + c0) = *(uint4*)hv;
        }

        // per-thread partial attention dots, reduce over 4 threads (same head)
        float ps = 0.f, pd = 0.f;
        #pragma unroll
        for (int j = 0; j < 8; j++) {
            ps += acc[i][j] * wsv[j];
            pd += acc[i][j] * wdv[j];
        }
        ps += __shfl_xor_sync(0xffffffffu, ps, 1);
        ps += __shfl_xor_sync(0xffffffffu, ps, 2);
        pd += __shfl_xor_sync(0xffffffffu, pd, 1);
        pd += __shfl_xor_sync(0xffffffffu, pd, 2);
        if ((tx & 3) == 0 && r < N) {
            a_s[r * 4 + head] = ps;
            a_d[r * 4 + head] = pd;
        }
    }
}

// ---------------------------------------------------------------------------
// edge-parallel softmax numerators: pw[i] = exp(leaky(a_s[src] + a_d[dst]))
// i iterates CSR order => csrd is near-sorted (a_d reads ~sequential),
// pw writes fully coalesced; only a_s is a random 16B fetch, MLP-rich.
__global__ void edge_score_kernel(const int* __restrict__ csrs,
                                  const int* __restrict__ csrd,
                                  const float* __restrict__ a_s,
                                  const float* __restrict__ a_d,
                                  float4* __restrict__ pw, int TOT)
{
    int i = blockIdx.x * blockDim.x + threadIdx.x;
    if (i >= TOT) return;
    int s = __ldg(csrs + i);
    int d = __ldg(csrd + i);
    float4 es = *(const float4*)(a_s + (size_t)s * 4);
    float4 ed = *(const float4*)(a_d + (size_t)d * 4);
    float e0 = es.x + ed.x, e1 = es.y + ed.y;
    float e2 = es.z + ed.z, e3 = es.w + ed.w;
    e0 = e0 > 0.f ? e0 : 0.2f * e0;
    e1 = e1 > 0.f ? e1 : 0.2f * e1;
    e2 = e2 > 0.f ? e2 : 0.2f * e2;
    e3 = e3 > 0.f ? e3 : 0.2f * e3;
    pw[i] = make_float4(__expf(e0), __expf(e1), __expf(e2), __expf(e3));
}

// ---------------------------------------------------------------------------
// GAT message pass, warp per destination node, CSR gather over fp16 messages
// with precomputed fp32 edge weights. Only dependent hop: csrs[e] -> gh row.
__global__ void gat_gather_kernel(const int* __restrict__ off,
                                  const int* __restrict__ csrs,
                                  const float4* __restrict__ pw,
                                  const __half* __restrict__ gh,
                                  const float* __restrict__ bias,
                                  float* __restrict__ hout,
                                  int N, int do_relu)
{
    int warp = (blockIdx.x * blockDim.x + threadIdx.x) >> 5;
    int lane = threadIdx.x & 31;
    if (warp >= N) return;
    int h = lane >> 3;
    int e0 = __ldg(off + warp), e1 = __ldg(off + warp + 1);

    float ax = 0.f, ay = 0.f, az = 0.f, aw = 0.f, den = 0.f;

    #pragma unroll 4
    for (int e = e0; e < e1; e++) {
        int s = __ldg(csrs + e);
        float4 p4 = __ldg(pw + e);
        float p = h == 0 ? p4.x : (h == 1 ? p4.y : (h == 2 ? p4.z : p4.w));
        den += p;
        uint2 raw = *(const uint2*)(gh + (size_t)s * 128 + lane * 4);
        float2 f0 = __half22float2(*(const __half2*)&raw.x);
        float2 f1 = __half22float2(*(const __half2*)&raw.y);
        ax += p * f0.x; ay += p * f0.y; az += p * f1.x; aw += p * f1.y;
    }

    float inv = 1.f / den;
    float4 b = *(const float4*)(bias + lane * 4);
    float4 v;
    v.x = ax * inv + b.x;
    v.y = ay * inv + b.y;
    v.z = az * inv + b.z;
    v.w = aw * inv + b.w;
    if (do_relu) {
        v.x = fmaxf(v.x, 0.f); v.y = fmaxf(v.y, 0.f);
        v.z = fmaxf(v.z, 0.f); v.w = fmaxf(v.w, 0.f);
    }
    *(float4*)(hout + (size_t)warp * 128 + lane * 4) = v;
}

// ---------------------------------------------------------------------------
// concat [128,64]+[128,64] -> [128,128] so both head MLP-1s run as one GEMM
__global__ void concat_kernel(const float* __restrict__ ew,
                              const float* __restrict__ eb,
                              const float* __restrict__ rw,
                              const float* __restrict__ rb,
                              float* __restrict__ wc,
                              float* __restrict__ bc)
{
    int idx = blockIdx.x * blockDim.x + threadIdx.x;
    if (idx >= 128 * 128) return;
    int k = idx >> 7, m = idx & 127;
    wc[idx] = (m < 64) ? ew[k * 64 + m] : rw[k * 64 + (m - 64)];
    if (idx < 128)
        bc[idx] = (idx < 64) ? eb[idx] : rb[idx - 64];
}

// ---------------------------------------------------------------------------
// final heads from t = [relu(h@ed_w1+b) | relu(h@rp_w1+b)] (warp per node)
__global__ void heads_kernel(const float* __restrict__ t,
                             const float* __restrict__ ew2,
                             const float* __restrict__ eb2,
                             const float* __restrict__ rw2,
                             const float* __restrict__ rb2,
                             float* __restrict__ out, int N)
{
    int warp = (blockIdx.x * blockDim.x + threadIdx.x) >> 5;
    int lane = threadIdx.x & 31;
    if (warp >= N) return;
    const float* tr = t + (size_t)warp * 128;
    float v1 = tr[lane], v2 = tr[32 + lane];
    float4 w1 = *(const float4*)(ew2 + lane * 4);
    float4 w2 = *(const float4*)(ew2 + (32 + lane) * 4);
    float a0 = v1 * w1.x + v2 * w2.x;
    float a1 = v1 * w1.y + v2 * w2.y;
    float a2 = v1 * w1.z + v2 * w2.z;
    float a3 = v1 * w1.w + v2 * w2.w;
    float r1 = tr[64 + lane], r2 = tr[96 + lane];
    float ar = r1 * __ldg(rw2 + lane) + r2 * __ldg(rw2 + 32 + lane);
    #pragma unroll
    for (int off = 16; off; off >>= 1) {
        a0 += __shfl_xor_sync(0xffffffffu, a0, off);
        a1 += __shfl_xor_sync(0xffffffffu, a1, off);
        a2 += __shfl_xor_sync(0xffffffffu, a2, off);
        a3 += __shfl_xor_sync(0xffffffffu, a3, off);
        ar += __shfl_xor_sync(0xffffffffu, ar, off);
    }
    if (lane == 0) {
        out[warp * 4 + 0] = a0 + eb2[0];
        out[warp * 4 + 1] = a1 + eb2[1];
        out[warp * 4 + 2] = a2 + eb2[2];
        out[warp * 4 + 3] = a3 + eb2[3];
        out[(size_t)N * 4 + warp] = ar + rb2[0];
    }
}

// ---------------------------------------------------------------------------
extern "C" void kernel_launch(void* const* d_in, const int* in_sizes, int n_in,
                              void* d_out, int out_size)
{
    const float* x     = (const float*)d_in[0];
    const void*  ei    = d_in[1];
    const float* ce_w1 = (const float*)d_in[2];
    const float* ce_b1 = (const float*)d_in[3];
    const float* ce_w2 = (const float*)d_in[4];
    const float* ce_b2 = (const float*)d_in[5];
    const float* ed_w1 = (const float*)d_in[14];
    const float* ed_b1 = (const float*)d_in[15];
    const float* ed_w2 = (const float*)d_in[16];
    const float* ed_b2 = (const float*)d_in[17];
    const float* rp_w1 = (const float*)d_in[18];
    const float* rp_b1 = (const float*)d_in[19];
    const float* rp_w2 = (const float*)d_in[20];
    const float* rp_b2 = (const float*)d_in[21];

    int N = in_sizes[0] / 8;
    int E = in_sizes[1] / 2;
    int TOT = E + N;

    float *t, *h, *as_, *ad_, *wcat, *bcat;
    __half* gh;
    float4* pw;
    int *off, *cur, *csrs, *csrd, *bsum;
    cudaGetSymbolAddress((void**)&t,    d_t);
    cudaGetSymbolAddress((void**)&h,    d_h);
    cudaGetSymbolAddress((void**)&gh,   d_gh);
    cudaGetSymbolAddress((void**)&as_,  d_as);
    cudaGetSymbolAddress((void**)&ad_,  d_ad);
    cudaGetSymbolAddress((void**)&wcat, d_wcat);
    cudaGetSymbolAddress((void**)&bcat, d_bcat);
    cudaGetSymbolAddress((void**)&off,  d_off);
    cudaGetSymbolAddress((void**)&cur,  d_cur);
    cudaGetSymbolAddress((void**)&csrs, d_csrs);
    cudaGetSymbolAddress((void**)&csrd, d_csrd);
    cudaGetSymbolAddress((void**)&pw,   d_pw);
    cudaGetSymbolAddress((void**)&bsum, d_bsum);

    detect_kernel<<<1, 32>>>((const int*)ei);

    // ---- CSR build (once, used by both GAT layers) ----
    cudaMemsetAsync(cur, 0, (size_t)N * sizeof(int), 0);
    hist_kernel<<<(TOT + 255) / 256, 256>>>(ei, E, N, cur);
    int nb = (N + 1023) / 1024;
    scan1_kernel<<<nb, 1024>>>(cur, off, bsum, N);
    scan2_kernel<<<1, 64>>>(bsum, nb);
    scan3_kernel<<<(N + 255) / 256, 256>>>(off, bsum, cur, N, TOT);
    scatter_kernel<<<(TOT + 255) / 256, 256>>>(ei, E, N, cur, csrs, csrd);

    // ---- cell encoder ----
    encoder1_kernel<<<(N * 128 + 255) / 256, 256>>>(x, ce_w1, ce_b1, t, N);
    gemm128_kernel<<<(N + 127) / 128, 256>>>(t, ce_w2, ce_b2, h, N, 0);

    // ---- two GAT layers ----
    for (int layer = 0; layer < 2; layer++) {
        const float* gw  = (const float*)d_in[layer ? 10 : 6];
        const float* gas = (const float*)d_in[layer ? 11 : 7];
        const float* gad = (const float*)d_in[layer ? 12 : 8];
        const float* gb  = (const float*)d_in[layer ? 13 : 9];

        gemm_gat_kernel<<<(N + 127) / 128, 256>>>(h, gw, gas, gad,
                                                  gh, as_, ad_, N);
        edge_score_kernel<<<(TOT + 255) / 256, 256>>>(csrs, csrd, as_, ad_,
                                                      pw, TOT);
        gat_gather_kernel<<<(N * 32 + 255) / 256, 256>>>(
            off, csrs, pw, gh, gb, h, N, layer == 0 ? 1 : 0);
    }

    // ---- output heads ----
    concat_kernel<<<(128 * 128 + 255) / 256, 256>>>(ed_w1, ed_b1, rp_w1, rp_b1,
                                                    wcat, bcat);
    gemm128_kernel<<<(N + 127) / 128, 256>>>(h, wcat, bcat, t, N, 1);
    heads_kernel<<<(N * 32 + 255) / 256, 256>>>(t, ed_w2, ed_b2, rp_w2, rp_b2,
                                                (float*)d_out, N);
}

// round 5
// speedup vs baseline: 1.3613x; 1.3613x over previous
#include <cuda_runtime.h>
#include <cuda_fp16.h>
#include <cstdint>

// ---------------------------------------------------------------------------
// TableGNN: encoder MLP -> GAT(4 heads x 32ch) -> ReLU -> GAT -> two head MLPs
// N=50000, E=1.6M (+N self loops), D=128.
// Round 5: back to R3 structure (inline exp in gather — edge-parallel scores
// regressed). Gather now half-warp-per-node with uint4 loads: warp serves two
// edges per instruction stream -> ~half the LDG/loop instructions per edge.
// ---------------------------------------------------------------------------

#define MAXN 50176
#define MAXE 1700000

__device__ float  d_t   [MAXN * 128];
__device__ float  d_h   [MAXN * 128];
__device__ __half d_gh  [MAXN * 128];
__device__ float  d_as  [MAXN * 4];
__device__ float  d_ad  [MAXN * 4];
__device__ float  d_wcat[128 * 128];
__device__ float  d_bcat[128];
__device__ int    d_off [MAXN + 1];
__device__ int    d_cur [MAXN];        // doubles as histogram counter
__device__ int    d_csrs[MAXE];
__device__ int    d_bsum[64];
__device__ int    d_is64;

// ---------------------------------------------------------------------------
// detect whether edge_index is int64 (odd 32-bit words all zero) or int32
__global__ void detect_kernel(const int* __restrict__ ei)
{
    if (threadIdx.x == 0 && blockIdx.x == 0) {
        int f = 1;
        #pragma unroll
        for (int i = 1; i < 64; i += 2)
            if (ei[i] != 0) f = 0;
        d_is64 = f;
    }
}

__device__ __forceinline__ void load_edge(const void* ei, int E, int N, int i,
                                          int& s, int& d)
{
    if (i < E) {
        if (d_is64) {
            const long long* p = (const long long*)ei;
            s = (int)__ldg(p + i);
            d = (int)__ldg(p + E + i);
        } else {
            const int* p = (const int*)ei;
            s = __ldg(p + i);
            d = __ldg(p + E + i);
        }
    } else {
        s = d = i - E;   // self loop
    }
}

// ---------------------------------------------------------------------------
// CSR build: histogram of dst (incl. self loops)
__global__ void hist_kernel(const void* __restrict__ ei, int E, int N,
                            int* __restrict__ cnt)
{
    int i = blockIdx.x * blockDim.x + threadIdx.x;
    if (i >= E + N) return;
    int s, d;
    load_edge(ei, E, N, i, s, d);
    atomicAdd(&cnt[d], 1);
}

// per-block exclusive scan (1024 elems), block totals to bsum
__global__ void scan1_kernel(const int* __restrict__ cnt,
                             int* __restrict__ off,
                             int* __restrict__ bsum, int N)
{
    __shared__ int sh[1024];
    int i = blockIdx.x * 1024 + threadIdx.x;
    int v = (i < N) ? cnt[i] : 0;
    sh[threadIdx.x] = v;
    __syncthreads();
    for (int s = 1; s < 1024; s <<= 1) {
        int t = (threadIdx.x >= s) ? sh[threadIdx.x - s] : 0;
        __syncthreads();
        sh[threadIdx.x] += t;
        __syncthreads();
    }
    if (i < N) off[i] = sh[threadIdx.x] - v;
    if (threadIdx.x == 1023) bsum[blockIdx.x] = sh[1023];
}

// block-sum prefix (redundant per block) + final offsets + cursor copy
__global__ void scan23_kernel(int* __restrict__ off,
                              const int* __restrict__ bsum,
                              int* __restrict__ cur, int N, int total, int nb)
{
    __shared__ int pre[64];
    if (threadIdx.x < 64)
        pre[threadIdx.x] = (threadIdx.x < nb) ? bsum[threadIdx.x] : 0;
    __syncthreads();
    if (threadIdx.x == 0) {
        int s = 0;
        for (int i = 0; i < nb; i++) { int v = pre[i]; pre[i] = s; s += v; }
    }
    __syncthreads();
    int i = blockIdx.x * blockDim.x + threadIdx.x;
    if (i < N) {
        int v = off[i] + pre[i >> 10];
        off[i] = v;
        cur[i] = v;
    }
    if (i == 0) off[N] = total;
}

// scatter src ids into CSR order
__global__ void scatter_kernel(const void* __restrict__ ei, int E, int N,
                               int* __restrict__ cur, int* __restrict__ csrs)
{
    int i = blockIdx.x * blockDim.x + threadIdx.x;
    if (i >= E + N) return;
    int s, d;
    load_edge(ei, E, N, i, s, d);
    int pos = atomicAdd(&cur[d], 1);
    csrs[pos] = s;
}

// ---------------------------------------------------------------------------
// t[n][c] = relu(b1[c] + sum_k x[n][k] * w1[k][c]), K=8
__global__ void encoder1_kernel(const float* __restrict__ x,
                                const float* __restrict__ w1,
                                const float* __restrict__ b1,
                                float* __restrict__ t, int N)
{
    int idx = blockIdx.x * blockDim.x + threadIdx.x;
    if (idx >= N * 128) return;
    int n = idx >> 7, c = idx & 127;
    float s = b1[c];
    #pragma unroll
    for (int k = 0; k < 8; k++)
        s += x[n * 8 + k] * w1[k * 128 + c];
    t[idx] = fmaxf(s, 0.f);
}

// ---------------------------------------------------------------------------
// fp32 GEMM: C[N,128] = act(A[N,128] @ W[128,128] + bias)
// 128x128 block tile, BK=16, 256 threads, 8x8 micro-tile, As transposed.
__launch_bounds__(256)
__global__ void gemm128_kernel(const float* __restrict__ A,
                               const float* __restrict__ W,
                               const float* __restrict__ bias,
                               float* __restrict__ C,
                               int N, int act)
{
    __shared__ float As[16][128];   // [k][m]
    __shared__ float Ws[16][128];   // [k][n]
    const int tid = threadIdx.x;
    const int rowBase = blockIdx.x * 128;
    const int tx = tid & 15, ty = tid >> 4;
    const int r0 = ty * 8, c0 = tx * 8;

    float acc[8][8];
    #pragma unroll
    for (int i = 0; i < 8; i++)
        #pragma unroll
        for (int j = 0; j < 8; j++) acc[i][j] = 0.f;

    const int arow = tid >> 1;
    const int akg  = (tid & 1) * 8;
    const int wk   = (tid * 8) >> 7;
    const int wn   = (tid * 8) & 127;

    for (int kc = 0; kc < 128; kc += 16) {
        float4 a0 = make_float4(0.f, 0.f, 0.f, 0.f);
        float4 a1 = make_float4(0.f, 0.f, 0.f, 0.f);
        if (rowBase + arow < N) {
            const float* ap = A + (size_t)(rowBase + arow) * 128 + kc + akg;
            a0 = *(const float4*)ap;
            a1 = *(const float4*)(ap + 4);
        }
        As[akg + 0][arow] = a0.x; As[akg + 1][arow] = a0.y;
        As[akg + 2][arow] = a0.z; As[akg + 3][arow] = a0.w;
        As[akg + 4][arow] = a1.x; As[akg + 5][arow] = a1.y;
        As[akg + 6][arow] = a1.z; As[akg + 7][arow] = a1.w;

        const float* wp = W + (size_t)(kc + wk) * 128 + wn;
        *(float4*)(&Ws[wk][wn])     = *(const float4*)wp;
        *(float4*)(&Ws[wk][wn + 4]) = *(const float4*)(wp + 4);
        __syncthreads();

        #pragma unroll
        for (int kk = 0; kk < 16; kk++) {
            float4 af0 = *(const float4*)(&As[kk][r0]);
            float4 af1 = *(const float4*)(&As[kk][r0 + 4]);
            float4 wf0 = *(const float4*)(&Ws[kk][c0]);
            float4 wf1 = *(const float4*)(&Ws[kk][c0 + 4]);
            float a[8] = {af0.x, af0.y, af0.z, af0.w, af1.x, af1.y, af1.z, af1.w};
            float w[8] = {wf0.x, wf0.y, wf0.z, wf0.w, wf1.x, wf1.y, wf1.z, wf1.w};
            #pragma unroll
            for (int i = 0; i < 8; i++)
                #pragma unroll
                for (int j = 0; j < 8; j++)
                    acc[i][j] += a[i] * w[j];
        }
        __syncthreads();
    }

    float b[8];
    #pragma unroll
    for (int j = 0; j < 8; j++) b[j] = bias ? bias[c0 + j] : 0.f;

    #pragma unroll
    for (int i = 0; i < 8; i++) {
        int r = rowBase + r0 + i;
        if (r < N) {
            float* cp = C + (size_t)r * 128 + c0;
            #pragma unroll
            for (int j = 0; j < 8; j++) {
                float v = acc[i][j] + b[j];
                if (act) v = fmaxf(v, 0.f);
                cp[j] = v;
            }
        }
    }
}

// ---------------------------------------------------------------------------
// GAT projection GEMM: G = h @ gw (no bias). Epilogue:
//  - writes G as fp16 (message tensor for the gather)
//  - computes a_s[n][h], a_d[n][h] from the fp32 accumulators (shfl reduce)
__launch_bounds__(256)
__global__ void gemm_gat_kernel(const float* __restrict__ A,
                                const float* __restrict__ W,
                                const float* __restrict__ ws,
                                const float* __restrict__ wd,
                                __half* __restrict__ gh,
                                float* __restrict__ a_s,
                                float* __restrict__ a_d,
                                int N)
{
    __shared__ float As[16][128];
    __shared__ float Ws[16][128];
    const int tid = threadIdx.x;
    const int rowBase = blockIdx.x * 128;
    const int tx = tid & 15, ty = tid >> 4;
    const int r0 = ty * 8, c0 = tx * 8;

    float acc[8][8];
    #pragma unroll
    for (int i = 0; i < 8; i++)
        #pragma unroll
        for (int j = 0; j < 8; j++) acc[i][j] = 0.f;

    const int arow = tid >> 1;
    const int akg  = (tid & 1) * 8;
    const int wk   = (tid * 8) >> 7;
    const int wn   = (tid * 8) & 127;

    for (int kc = 0; kc < 128; kc += 16) {
        float4 a0 = make_float4(0.f, 0.f, 0.f, 0.f);
        float4 a1 = make_float4(0.f, 0.f, 0.f, 0.f);
        if (rowBase + arow < N) {
            const float* ap = A + (size_t)(rowBase + arow) * 128 + kc + akg;
            a0 = *(const float4*)ap;
            a1 = *(const float4*)(ap + 4);
        }
        As[akg + 0][arow] = a0.x; As[akg + 1][arow] = a0.y;
        As[akg + 2][arow] = a0.z; As[akg + 3][arow] = a0.w;
        As[akg + 4][arow] = a1.x; As[akg + 5][arow] = a1.y;
        As[akg + 6][arow] = a1.z; As[akg + 7][arow] = a1.w;

        const float* wp = W + (size_t)(kc + wk) * 128 + wn;
        *(float4*)(&Ws[wk][wn])     = *(const float4*)wp;
        *(float4*)(&Ws[wk][wn + 4]) = *(const float4*)(wp + 4);
        __syncthreads();

        #pragma unroll
        for (int kk = 0; kk < 16; kk++) {
            float4 af0 = *(const float4*)(&As[kk][r0]);
            float4 af1 = *(const float4*)(&As[kk][r0 + 4]);
            float4 wf0 = *(const float4*)(&Ws[kk][c0]);
            float4 wf1 = *(const float4*)(&Ws[kk][c0 + 4]);
            float a[8] = {af0.x, af0.y, af0.z, af0.w, af1.x, af1.y, af1.z, af1.w};
            float w[8] = {wf0.x, wf0.y, wf0.z, wf0.w, wf1.x, wf1.y, wf1.z, wf1.w};
            #pragma unroll
            for (int i = 0; i < 8; i++)
                #pragma unroll
                for (int j = 0; j < 8; j++)
                    acc[i][j] += a[i] * w[j];
        }
        __syncthreads();
    }

    // attention-vector slices for this thread's 8 columns
    float wsv[8], wdv[8];
    #pragma unroll
    for (int j = 0; j < 8; j++) {
        wsv[j] = __ldg(ws + c0 + j);
        wdv[j] = __ldg(wd + c0 + j);
    }

    const int head = tx >> 2;   // 8-col group never crosses a 32-ch head

    #pragma unroll
    for (int i = 0; i < 8; i++) {
        int r = rowBase + r0 + i;

        // fp16 message row segment
        if (r < N) {
            __half2 hv[4];
            #pragma unroll
            for (int j = 0; j < 4; j++)
                hv[j] = __floats2half2_rn(acc[i][2 * j], acc[i][2 * j + 1]);
            *(uint4*)(gh + (size_t)r * 128 + c0) = *(uint4*)hv;
        }

        // per-thread partial attention dots, reduce over 4 threads (same head)
        float ps = 0.f, pd = 0.f;
        #pragma unroll
        for (int j = 0; j < 8; j++) {
            ps += acc[i][j] * wsv[j];
            pd += acc[i][j] * wdv[j];
        }
        ps += __shfl_xor_sync(0xffffffffu, ps, 1);
        ps += __shfl_xor_sync(0xffffffffu, ps, 2);
        pd += __shfl_xor_sync(0xffffffffu, pd, 1);
        pd += __shfl_xor_sync(0xffffffffu, pd, 2);
        if ((tx & 3) == 0 && r < N) {
            a_s[r * 4 + head] = ps;
            a_d[r * 4 + head] = pd;
        }
    }
}

// ---------------------------------------------------------------------------
// GAT message pass: HALF-WARP per destination node. lane16 = lane&15 covers
// channels lane16*8..+7 (head = lane16>>2) via one uint4 (8 fp16) load.
// Each warp-wide instruction serves two edges (one per half-warp).
__global__ void gat_gather_kernel(const int* __restrict__ off,
                                  const int* __restrict__ csrs,
                                  const float* __restrict__ a_s,
                                  const float* __restrict__ a_d,
                                  const __half* __restrict__ gh,
                                  const float* __restrict__ bias,
                                  float* __restrict__ hout,
                                  int N, int do_relu)
{
    int node = (blockIdx.x * blockDim.x + threadIdx.x) >> 4;
    int lane = threadIdx.x & 15;
    if (node >= N) return;
    int h = lane >> 2;
    float ad = __ldg(a_d + node * 4 + h);
    int e0 = __ldg(off + node), e1 = __ldg(off + node + 1);

    float acc[8];
    #pragma unroll
    for (int j = 0; j < 8; j++) acc[j] = 0.f;
    float den = 0.f;

    #pragma unroll 4
    for (int e = e0; e < e1; e++) {
        int s = __ldg(csrs + e);
        float ev = __ldg(a_s + s * 4 + h) + ad;
        ev = ev > 0.f ? ev : 0.2f * ev;
        float p = __expf(ev);
        den += p;
        uint4 raw = *(const uint4*)(gh + (size_t)s * 128 + lane * 8);
        float2 f0 = __half22float2(*(const __half2*)&raw.x);
        float2 f1 = __half22float2(*(const __half2*)&raw.y);
        float2 f2 = __half22float2(*(const __half2*)&raw.z);
        float2 f3 = __half22float2(*(const __half2*)&raw.w);
        acc[0] += p * f0.x; acc[1] += p * f0.y;
        acc[2] += p * f1.x; acc[3] += p * f1.y;
        acc[4] += p * f2.x; acc[5] += p * f2.y;
        acc[6] += p * f3.x; acc[7] += p * f3.y;
    }

    float inv = 1.f / den;
    float4 b0 = *(const float4*)(bias + lane * 8);
    float4 b1 = *(const float4*)(bias + lane * 8 + 4);
    float4 v0, v1;
    v0.x = acc[0] * inv + b0.x; v0.y = acc[1] * inv + b0.y;
    v0.z = acc[2] * inv + b0.z; v0.w = acc[3] * inv + b0.w;
    v1.x = acc[4] * inv + b1.x; v1.y = acc[5] * inv + b1.y;
    v1.z = acc[6] * inv + b1.z; v1.w = acc[7] * inv + b1.w;
    if (do_relu) {
        v0.x = fmaxf(v0.x, 0.f); v0.y = fmaxf(v0.y, 0.f);
        v0.z = fmaxf(v0.z, 0.f); v0.w = fmaxf(v0.w, 0.f);
        v1.x = fmaxf(v1.x, 0.f); v1.y = fmaxf(v1.y, 0.f);
        v1.z = fmaxf(v1.z, 0.f); v1.w = fmaxf(v1.w, 0.f);
    }
    float* hp = hout + (size_t)node * 128 + lane * 8;
    *(float4*)hp       = v0;
    *(float4*)(hp + 4) = v1;
}

// ---------------------------------------------------------------------------
// concat [128,64]+[128,64] -> [128,128] so both head MLP-1s run as one GEMM
__global__ void concat_kernel(const float* __restrict__ ew,
                              const float* __restrict__ eb,
                              const float* __restrict__ rw,
                              const float* __restrict__ rb,
                              float* __restrict__ wc,
                              float* __restrict__ bc)
{
    int idx = blockIdx.x * blockDim.x + threadIdx.x;
    if (idx >= 128 * 128) return;
    int k = idx >> 7, m = idx & 127;
    wc[idx] = (m < 64) ? ew[k * 64 + m] : rw[k * 64 + (m - 64)];
    if (idx < 128)
        bc[idx] = (idx < 64) ? eb[idx] : rb[idx - 64];
}

// ---------------------------------------------------------------------------
// final heads from t = [relu(h@ed_w1+b) | relu(h@rp_w1+b)] (warp per node)
__global__ void heads_kernel(const float* __restrict__ t,
                             const float* __restrict__ ew2,
                             const float* __restrict__ eb2,
                             const float* __restrict__ rw2,
                             const float* __restrict__ rb2,
                             float* __restrict__ out, int N)
{
    int warp = (blockIdx.x * blockDim.x + threadIdx.x) >> 5;
    int lane = threadIdx.x & 31;
    if (warp >= N) return;
    const float* tr = t + (size_t)warp * 128;
    float v1 = tr[lane], v2 = tr[32 + lane];
    float4 w1 = *(const float4*)(ew2 + lane * 4);
    float4 w2 = *(const float4*)(ew2 + (32 + lane) * 4);
    float a0 = v1 * w1.x + v2 * w2.x;
    float a1 = v1 * w1.y + v2 * w2.y;
    float a2 = v1 * w1.z + v2 * w2.z;
    float a3 = v1 * w1.w + v2 * w2.w;
    float r1 = tr[64 + lane], r2 = tr[96 + lane];
    float ar = r1 * __ldg(rw2 + lane) + r2 * __ldg(rw2 + 32 + lane);
    #pragma unroll
    for (int off = 16; off; off >>= 1) {
        a0 += __shfl_xor_sync(0xffffffffu, a0, off);
        a1 += __shfl_xor_sync(0xffffffffu, a1, off);
        a2 += __shfl_xor_sync(0xffffffffu, a2, off);
        a3 += __shfl_xor_sync(0xffffffffu, a3, off);
        ar += __shfl_xor_sync(0xffffffffu, ar, off);
    }
    if (lane == 0) {
        out[warp * 4 + 0] = a0 + eb2[0];
        out[warp * 4 + 1] = a1 + eb2[1];
        out[warp * 4 + 2] = a2 + eb2[2];
        out[warp * 4 + 3] = a3 + eb2[3];
        out[(size_t)N * 4 + warp] = ar + rb2[0];
    }
}

// ---------------------------------------------------------------------------
extern "C" void kernel_launch(void* const* d_in, const int* in_sizes, int n_in,
                              void* d_out, int out_size)
{
    const float* x     = (const float*)d_in[0];
    const void*  ei    = d_in[1];
    const float* ce_w1 = (const float*)d_in[2];
    const float* ce_b1 = (const float*)d_in[3];
    const float* ce_w2 = (const float*)d_in[4];
    const float* ce_b2 = (const float*)d_in[5];
    const float* ed_w1 = (const float*)d_in[14];
    const float* ed_b1 = (const float*)d_in[15];
    const float* ed_w2 = (const float*)d_in[16];
    const float* ed_b2 = (const float*)d_in[17];
    const float* rp_w1 = (const float*)d_in[18];
    const float* rp_b1 = (const float*)d_in[19];
    const float* rp_w2 = (const float*)d_in[20];
    const float* rp_b2 = (const float*)d_in[21];

    int N = in_sizes[0] / 8;
    int E = in_sizes[1] / 2;
    int TOT = E + N;

    float *t, *h, *as_, *ad_, *wcat, *bcat;
    __half* gh;
    int *off, *cur, *csrs, *bsum;
    cudaGetSymbolAddress((void**)&t,    d_t);
    cudaGetSymbolAddress((void**)&h,    d_h);
    cudaGetSymbolAddress((void**)&gh,   d_gh);
    cudaGetSymbolAddress((void**)&as_,  d_as);
    cudaGetSymbolAddress((void**)&ad_,  d_ad);
    cudaGetSymbolAddress((void**)&wcat, d_wcat);
    cudaGetSymbolAddress((void**)&bcat, d_bcat);
    cudaGetSymbolAddress((void**)&off,  d_off);
    cudaGetSymbolAddress((void**)&cur,  d_cur);
    cudaGetSymbolAddress((void**)&csrs, d_csrs);
    cudaGetSymbolAddress((void**)&bsum, d_bsum);

    detect_kernel<<<1, 32>>>((const int*)ei);

    // ---- CSR build (once, used by both GAT layers) ----
    cudaMemsetAsync(cur, 0, (size_t)N * sizeof(int), 0);
    hist_kernel<<<(TOT + 255) / 256, 256>>>(ei, E, N, cur);
    int nb = (N + 1023) / 1024;
    scan1_kernel<<<nb, 1024>>>(cur, off, bsum, N);
    scan23_kernel<<<(N + 255) / 256, 256>>>(off, bsum, cur, N, TOT, nb);
    scatter_kernel<<<(TOT + 255) / 256, 256>>>(ei, E, N, cur, csrs);

    // ---- cell encoder ----
    encoder1_kernel<<<(N * 128 + 255) / 256, 256>>>(x, ce_w1, ce_b1, t, N);
    gemm128_kernel<<<(N + 127) / 128, 256>>>(t, ce_w2, ce_b2, h, N, 0);

    // ---- two GAT layers ----
    for (int layer = 0; layer < 2; layer++) {
        const float* gw  = (const float*)d_in[layer ? 10 : 6];
        const float* gas = (const float*)d_in[layer ? 11 : 7];
        const float* gad = (const float*)d_in[layer ? 12 : 8];
        const float* gb  = (const float*)d_in[layer ? 13 : 9];

        gemm_gat_kernel<<<(N + 127) / 128, 256>>>(h, gw, gas, gad,
                                                  gh, as_, ad_, N);
        gat_gather_kernel<<<(N * 16 + 255) / 256, 256>>>(
            off, csrs, as_, ad_, gh, gb, h, N, layer == 0 ? 1 : 0);
    }

    // ---- output heads ----
    concat_kernel<<<(128 * 128 + 255) / 256, 256>>>(ed_w1, ed_b1, rp_w1, rp_b1,
                                                    wcat, bcat);
    gemm128_kernel<<<(N + 127) / 128, 256>>>(h, wcat, bcat, t, N, 1);
    heads_kernel<<<(N * 32 + 255) / 256, 256>>>(t, ed_w2, ed_b2, rp_w2, rp_b2,
                                                (float*)d_out, N);
}

// round 6
// speedup vs baseline: 1.8642x; 1.3695x over previous
#include <cuda_runtime.h>
#include <cuda_fp16.h>
#include <cstdint>

// ---------------------------------------------------------------------------
// TableGNN: encoder MLP -> GAT(4 heads x 32ch) -> ReLU -> GAT -> two head MLPs
// N=50000, E=1.6M (+N self loops), D=128.
// Round 6: tf32 mma.sync GEMMs (fused GAT epilogue via documented fragment
// mapping), quarter-warp CSR gather over fp16 messages.
// ---------------------------------------------------------------------------

#define MAXN 50176
#define MAXE 1700000

__device__ float  d_t   [MAXN * 128];
__device__ float  d_h   [MAXN * 128];
__device__ __half d_gh  [MAXN * 128];
__device__ float  d_as  [MAXN * 4];
__device__ float  d_ad  [MAXN * 4];
__device__ float  d_wcat[128 * 128];
__device__ float  d_bcat[128];
__device__ int    d_off [MAXN + 1];
__device__ int    d_cur [MAXN];
__device__ int    d_csrs[MAXE];
__device__ int    d_bsum[64];
__device__ int    d_is64;

// ---------------------------------------------------------------------------
__global__ void detect_kernel(const int* __restrict__ ei)
{
    if (threadIdx.x == 0 && blockIdx.x == 0) {
        int f = 1;
        #pragma unroll
        for (int i = 1; i < 64; i += 2)
            if (ei[i] != 0) f = 0;
        d_is64 = f;
    }
}

__device__ __forceinline__ void load_edge(const void* ei, int E, int N, int i,
                                          int& s, int& d)
{
    if (i < E) {
        if (d_is64) {
            const long long* p = (const long long*)ei;
            s = (int)__ldg(p + i);
            d = (int)__ldg(p + E + i);
        } else {
            const int* p = (const int*)ei;
            s = __ldg(p + i);
            d = __ldg(p + E + i);
        }
    } else {
        s = d = i - E;
    }
}

// ---------------------------------------------------------------------------
__global__ void hist_kernel(const void* __restrict__ ei, int E, int N,
                            int* __restrict__ cnt)
{
    int i = blockIdx.x * blockDim.x + threadIdx.x;
    if (i >= E + N) return;
    int s, d;
    load_edge(ei, E, N, i, s, d);
    atomicAdd(&cnt[d], 1);
}

__global__ void scan1_kernel(const int* __restrict__ cnt,
                             int* __restrict__ off,
                             int* __restrict__ bsum, int N)
{
    __shared__ int sh[1024];
    int i = blockIdx.x * 1024 + threadIdx.x;
    int v = (i < N) ? cnt[i] : 0;
    sh[threadIdx.x] = v;
    __syncthreads();
    for (int s = 1; s < 1024; s <<= 1) {
        int t = (threadIdx.x >= s) ? sh[threadIdx.x - s] : 0;
        __syncthreads();
        sh[threadIdx.x] += t;
        __syncthreads();
    }
    if (i < N) off[i] = sh[threadIdx.x] - v;
    if (threadIdx.x == 1023) bsum[blockIdx.x] = sh[1023];
}

__global__ void scan23_kernel(int* __restrict__ off,
                              const int* __restrict__ bsum,
                              int* __restrict__ cur, int N, int total, int nb)
{
    __shared__ int pre[64];
    if (threadIdx.x < 64)
        pre[threadIdx.x] = (threadIdx.x < nb) ? bsum[threadIdx.x] : 0;
    __syncthreads();
    if (threadIdx.x == 0) {
        int s = 0;
        for (int i = 0; i < nb; i++) { int v = pre[i]; pre[i] = s; s += v; }
    }
    __syncthreads();
    int i = blockIdx.x * blockDim.x + threadIdx.x;
    if (i < N) {
        int v = off[i] + pre[i >> 10];
        off[i] = v;
        cur[i] = v;
    }
    if (i == 0) off[N] = total;
}

__global__ void scatter_kernel(const void* __restrict__ ei, int E, int N,
                               int* __restrict__ cur, int* __restrict__ csrs)
{
    int i = blockIdx.x * blockDim.x + threadIdx.x;
    if (i >= E + N) return;
    int s, d;
    load_edge(ei, E, N, i, s, d);
    int pos = atomicAdd(&cur[d], 1);
    csrs[pos] = s;
}

// ---------------------------------------------------------------------------
// t[n][c] = relu(b1[c] + sum_k x[n][k] * w1[k][c]), K=8
__global__ void encoder1_kernel(const float* __restrict__ x,
                                const float* __restrict__ w1,
                                const float* __restrict__ b1,
                                float* __restrict__ t, int N)
{
    int idx = blockIdx.x * blockDim.x + threadIdx.x;
    if (idx >= N * 128) return;
    int n = idx >> 7, c = idx & 127;
    float s = b1[c];
    #pragma unroll
    for (int k = 0; k < 8; k++)
        s += x[n * 8 + k] * w1[k * 128 + c];
    t[idx] = fmaxf(s, 0.f);
}

// ---------------------------------------------------------------------------
// tf32 mma helpers
__device__ __forceinline__ uint32_t f2tf32(float f)
{
    uint32_t r;
    asm("cvt.rna.tf32.f32 %0, %1;" : "=r"(r) : "f"(f));
    return r;
}

__device__ __forceinline__ void mma_tf32(float c[4],
                                         uint32_t a0, uint32_t a1,
                                         uint32_t a2, uint32_t a3,
                                         uint32_t b0, uint32_t b1)
{
    asm volatile(
        "mma.sync.aligned.m16n8k8.row.col.f32.tf32.tf32.f32 "
        "{%0,%1,%2,%3}, {%4,%5,%6,%7}, {%8,%9}, {%0,%1,%2,%3};"
        : "+f"(c[0]), "+f"(c[1]), "+f"(c[2]), "+f"(c[3])
        : "r"(a0), "r"(a1), "r"(a2), "r"(a3), "r"(b0), "r"(b1));
}

#define SPITCH 136   // smem row pitch (floats): 136 mod 32 == 8 -> conflict-free frags

// Core: c[16][4] = A[128 rows @ rowBase][128] @ W[128][128] for this block.
// Block: 256 threads = 8 warps; warp w covers rows w*16..w*16+15.
// Buffers A (device-global scratch, MAXN rows) need no row guards.
__device__ __forceinline__ void gemm_tf32_core(const float* __restrict__ A,
                                               const float* __restrict__ W,
                                               int rowBase,
                                               uint32_t* As, uint32_t* Bs,
                                               float c[16][4])
{
    const int tid  = threadIdx.x;
    const int warp = tid >> 5, lane = tid & 31;
    const int grp  = lane >> 2, ctg = lane & 3;
    const int wrow = warp * 16;

    const int arow = tid >> 1;          // 0..127
    const int ah   = (tid & 1) * 16;    // 0 or 16

    for (int kc = 0; kc < 128; kc += 32) {
        // stage A (transposed, tf32)
        {
            const float* ap = A + (size_t)(rowBase + arow) * 128 + kc + ah;
            float av[16];
            *(float4*)(av + 0)  = *(const float4*)(ap + 0);
            *(float4*)(av + 4)  = *(const float4*)(ap + 4);
            *(float4*)(av + 8)  = *(const float4*)(ap + 8);
            *(float4*)(av + 12) = *(const float4*)(ap + 12);
            #pragma unroll
            for (int j = 0; j < 16; j++)
                As[(ah + j) * SPITCH + arow] = f2tf32(av[j]);
        }
        // stage B (tf32)
        #pragma unroll
        for (int it = 0; it < 4; it++) {
            int flat = tid * 4 + it * 1024;
            int bk = flat >> 7, bn = flat & 127;
            float4 wv = *(const float4*)(W + (size_t)(kc + bk) * 128 + bn);
            uint32_t* bp = Bs + bk * SPITCH + bn;
            bp[0] = f2tf32(wv.x); bp[1] = f2tf32(wv.y);
            bp[2] = f2tf32(wv.z); bp[3] = f2tf32(wv.w);
        }
        __syncthreads();

        #pragma unroll
        for (int k8 = 0; k8 < 4; k8++) {
            int kb = k8 * 8;
            uint32_t a0 = As[(kb + ctg) * SPITCH + wrow + grp];
            uint32_t a1 = As[(kb + ctg) * SPITCH + wrow + grp + 8];
            uint32_t a2 = As[(kb + ctg + 4) * SPITCH + wrow + grp];
            uint32_t a3 = As[(kb + ctg + 4) * SPITCH + wrow + grp + 8];
            #pragma unroll
            for (int nt = 0; nt < 16; nt++) {
                uint32_t b0 = Bs[(kb + ctg) * SPITCH + nt * 8 + grp];
                uint32_t b1 = Bs[(kb + ctg + 4) * SPITCH + nt * 8 + grp];
                mma_tf32(c[nt], a0, a1, a2, a3, b0, b1);
            }
        }
        __syncthreads();
    }
}

// plain tf32 GEMM: C = act(A @ W + bias)
__launch_bounds__(256)
__global__ void gemm_tf32_kernel(const float* __restrict__ A,
                                 const float* __restrict__ W,
                                 const float* __restrict__ bias,
                                 float* __restrict__ C,
                                 int act)
{
    __shared__ uint32_t As[32 * SPITCH];
    __shared__ uint32_t Bs[32 * SPITCH];
    float c[16][4];
    #pragma unroll
    for (int i = 0; i < 16; i++)
        #pragma unroll
        for (int j = 0; j < 4; j++) c[i][j] = 0.f;

    const int lane = threadIdx.x & 31;
    const int grp = lane >> 2, ctg = lane & 3;
    const int wrow = (threadIdx.x >> 5) * 16;
    const int rowBase = blockIdx.x * 128;

    gemm_tf32_core(A, W, rowBase, As, Bs, c);

    int r = rowBase + wrow + grp;       // rows r and r+8 (< MAXN, no guard)
    #pragma unroll
    for (int nt = 0; nt < 16; nt++) {
        int col = nt * 8 + ctg * 2;
        float bx = bias ? __ldg(bias + col) : 0.f;
        float by = bias ? __ldg(bias + col + 1) : 0.f;
        float2 lo = make_float2(c[nt][0] + bx, c[nt][1] + by);
        float2 hi = make_float2(c[nt][2] + bx, c[nt][3] + by);
        if (act) {
            lo.x = fmaxf(lo.x, 0.f); lo.y = fmaxf(lo.y, 0.f);
            hi.x = fmaxf(hi.x, 0.f); hi.y = fmaxf(hi.y, 0.f);
        }
        *(float2*)(C + (size_t)r * 128 + col) = lo;
        *(float2*)(C + (size_t)(r + 8) * 128 + col) = hi;
    }
}

// GAT projection GEMM (tf32): writes fp16 messages + attention scores.
__launch_bounds__(256)
__global__ void gemm_gat_tf32_kernel(const float* __restrict__ A,
                                     const float* __restrict__ W,
                                     const float* __restrict__ ws,
                                     const float* __restrict__ wd,
                                     __half* __restrict__ gh,
                                     float* __restrict__ a_s,
                                     float* __restrict__ a_d)
{
    __shared__ uint32_t As[32 * SPITCH];
    __shared__ uint32_t Bs[32 * SPITCH];
    float c[16][4];
    #pragma unroll
    for (int i = 0; i < 16; i++)
        #pragma unroll
        for (int j = 0; j < 4; j++) c[i][j] = 0.f;

    const int lane = threadIdx.x & 31;
    const int grp = lane >> 2, ctg = lane & 3;
    const int wrow = (threadIdx.x >> 5) * 16;
    const int rowBase = blockIdx.x * 128;

    gemm_tf32_core(A, W, rowBase, As, Bs, c);

    int r = rowBase + wrow + grp;

    float psl[4] = {0, 0, 0, 0}, pdl[4] = {0, 0, 0, 0};
    float psh[4] = {0, 0, 0, 0}, pdh[4] = {0, 0, 0, 0};

    #pragma unroll
    for (int nt = 0; nt < 16; nt++) {
        int col = nt * 8 + ctg * 2;
        float w0s = __ldg(ws + col), w1s = __ldg(ws + col + 1);
        float w0d = __ldg(wd + col), w1d = __ldg(wd + col + 1);
        int h = nt >> 2;
        psl[h] += c[nt][0] * w0s + c[nt][1] * w1s;
        pdl[h] += c[nt][0] * w0d + c[nt][1] * w1d;
        psh[h] += c[nt][2] * w0s + c[nt][3] * w1s;
        pdh[h] += c[nt][2] * w0d + c[nt][3] * w1d;

        *(__half2*)(gh + (size_t)r * 128 + col) =
            __floats2half2_rn(c[nt][0], c[nt][1]);
        *(__half2*)(gh + (size_t)(r + 8) * 128 + col) =
            __floats2half2_rn(c[nt][2], c[nt][3]);
    }

    // reduce over the 4 lanes (ctg) sharing each row
    #pragma unroll
    for (int h = 0; h < 4; h++) {
        psl[h] += __shfl_xor_sync(0xffffffffu, psl[h], 1);
        psl[h] += __shfl_xor_sync(0xffffffffu, psl[h], 2);
        pdl[h] += __shfl_xor_sync(0xffffffffu, pdl[h], 1);
        pdl[h] += __shfl_xor_sync(0xffffffffu, pdl[h], 2);
        psh[h] += __shfl_xor_sync(0xffffffffu, psh[h], 1);
        psh[h] += __shfl_xor_sync(0xffffffffu, psh[h], 2);
        pdh[h] += __shfl_xor_sync(0xffffffffu, pdh[h], 1);
        pdh[h] += __shfl_xor_sync(0xffffffffu, pdh[h], 2);
    }
    if (ctg == 0) {
        *(float4*)(a_s + (size_t)r * 4) = make_float4(psl[0], psl[1], psl[2], psl[3]);
        *(float4*)(a_d + (size_t)r * 4) = make_float4(pdl[0], pdl[1], pdl[2], pdl[3]);
        *(float4*)(a_s + (size_t)(r + 8) * 4) = make_float4(psh[0], psh[1], psh[2], psh[3]);
        *(float4*)(a_d + (size_t)(r + 8) * 4) = make_float4(pdh[0], pdh[1], pdh[2], pdh[3]);
    }
}

// ---------------------------------------------------------------------------
// GAT message pass: QUARTER-WARP per destination node. lane8 covers channels
// lane8*16..+15 (head = lane8>>1) via two uint4 (16 fp16) loads.
__global__ void gat_gather_kernel(const int* __restrict__ off,
                                  const int* __restrict__ csrs,
                                  const float* __restrict__ a_s,
                                  const float* __restrict__ a_d,
                                  const __half* __restrict__ gh,
                                  const float* __restrict__ bias,
                                  float* __restrict__ hout,
                                  int N, int do_relu)
{
    int node = (blockIdx.x * blockDim.x + threadIdx.x) >> 3;
    int lane = threadIdx.x & 7;
    if (node >= N) return;
    int h = lane >> 1;
    float ad = __ldg(a_d + node * 4 + h);
    int e0 = __ldg(off + node), e1 = __ldg(off + node + 1);

    float acc[16];
    #pragma unroll
    for (int j = 0; j < 16; j++) acc[j] = 0.f;
    float den = 0.f;

    #pragma unroll 4
    for (int e = e0; e < e1; e++) {
        int s = __ldg(csrs + e);
        float ev = __ldg(a_s + s * 4 + h) + ad;
        ev = ev > 0.f ? ev : 0.2f * ev;
        float p = __expf(ev);
        den += p;
        const uint4* gp = (const uint4*)(gh + (size_t)s * 128 + lane * 16);
        uint4 r0 = __ldg(gp);
        uint4 r1 = __ldg(gp + 1);
        const __half2* hp0 = (const __half2*)&r0;
        const __half2* hp1 = (const __half2*)&r1;
        #pragma unroll
        for (int j = 0; j < 4; j++) {
            float2 f = __half22float2(hp0[j]);
            acc[2 * j]     += p * f.x;
            acc[2 * j + 1] += p * f.y;
        }
        #pragma unroll
        for (int j = 0; j < 4; j++) {
            float2 f = __half22float2(hp1[j]);
            acc[8 + 2 * j]     += p * f.x;
            acc[8 + 2 * j + 1] += p * f.y;
        }
    }

    float inv = 1.f / den;
    float* hp = hout + (size_t)node * 128 + lane * 16;
    #pragma unroll
    for (int q = 0; q < 4; q++) {
        float4 b = *(const float4*)(bias + lane * 16 + q * 4);
        float4 v;
        v.x = acc[q * 4 + 0] * inv + b.x;
        v.y = acc[q * 4 + 1] * inv + b.y;
        v.z = acc[q * 4 + 2] * inv + b.z;
        v.w = acc[q * 4 + 3] * inv + b.w;
        if (do_relu) {
            v.x = fmaxf(v.x, 0.f); v.y = fmaxf(v.y, 0.f);
            v.z = fmaxf(v.z, 0.f); v.w = fmaxf(v.w, 0.f);
        }
        *(float4*)(hp + q * 4) = v;
    }
}

// ---------------------------------------------------------------------------
__global__ void concat_kernel(const float* __restrict__ ew,
                              const float* __restrict__ eb,
                              const float* __restrict__ rw,
                              const float* __restrict__ rb,
                              float* __restrict__ wc,
                              float* __restrict__ bc)
{
    int idx = blockIdx.x * blockDim.x + threadIdx.x;
    if (idx >= 128 * 128) return;
    int k = idx >> 7, m = idx & 127;
    wc[idx] = (m < 64) ? ew[k * 64 + m] : rw[k * 64 + (m - 64)];
    if (idx < 128)
        bc[idx] = (idx < 64) ? eb[idx] : rb[idx - 64];
}

// ---------------------------------------------------------------------------
__global__ void heads_kernel(const float* __restrict__ t,
                             const float* __restrict__ ew2,
                             const float* __restrict__ eb2,
                             const float* __restrict__ rw2,
                             const float* __restrict__ rb2,
                             float* __restrict__ out, int N)
{
    int warp = (blockIdx.x * blockDim.x + threadIdx.x) >> 5;
    int lane = threadIdx.x & 31;
    if (warp >= N) return;
    const float* tr = t + (size_t)warp * 128;
    float v1 = tr[lane], v2 = tr[32 + lane];
    float4 w1 = *(const float4*)(ew2 + lane * 4);
    float4 w2 = *(const float4*)(ew2 + (32 + lane) * 4);
    float a0 = v1 * w1.x + v2 * w2.x;
    float a1 = v1 * w1.y + v2 * w2.y;
    float a2 = v1 * w1.z + v2 * w2.z;
    float a3 = v1 * w1.w + v2 * w2.w;
    float r1 = tr[64 + lane], r2 = tr[96 + lane];
    float ar = r1 * __ldg(rw2 + lane) + r2 * __ldg(rw2 + 32 + lane);
    #pragma unroll
    for (int off = 16; off; off >>= 1) {
        a0 += __shfl_xor_sync(0xffffffffu, a0, off);
        a1 += __shfl_xor_sync(0xffffffffu, a1, off);
        a2 += __shfl_xor_sync(0xffffffffu, a2, off);
        a3 += __shfl_xor_sync(0xffffffffu, a3, off);
        ar += __shfl_xor_sync(0xffffffffu, ar, off);
    }
    if (lane == 0) {
        out[warp * 4 + 0] = a0 + eb2[0];
        out[warp * 4 + 1] = a1 + eb2[1];
        out[warp * 4 + 2] = a2 + eb2[2];
        out[warp * 4 + 3] = a3 + eb2[3];
        out[(size_t)N * 4 + warp] = ar + rb2[0];
    }
}

// ---------------------------------------------------------------------------
extern "C" void kernel_launch(void* const* d_in, const int* in_sizes, int n_in,
                              void* d_out, int out_size)
{
    const float* x     = (const float*)d_in[0];
    const void*  ei    = d_in[1];
    const float* ce_w1 = (const float*)d_in[2];
    const float* ce_b1 = (const float*)d_in[3];
    const float* ce_w2 = (const float*)d_in[4];
    const float* ce_b2 = (const float*)d_in[5];
    const float* ed_w1 = (const float*)d_in[14];
    const float* ed_b1 = (const float*)d_in[15];
    const float* ed_w2 = (const float*)d_in[16];
    const float* ed_b2 = (const float*)d_in[17];
    const float* rp_w1 = (const float*)d_in[18];
    const float* rp_b1 = (const float*)d_in[19];
    const float* rp_w2 = (const float*)d_in[20];
    const float* rp_b2 = (const float*)d_in[21];

    int N = in_sizes[0] / 8;
    int E = in_sizes[1] / 2;
    int TOT = E + N;

    float *t, *h, *as_, *ad_, *wcat, *bcat;
    __half* gh;
    int *off, *cur, *csrs, *bsum;
    cudaGetSymbolAddress((void**)&t,    d_t);
    cudaGetSymbolAddress((void**)&h,    d_h);
    cudaGetSymbolAddress((void**)&gh,   d_gh);
    cudaGetSymbolAddress((void**)&as_,  d_as);
    cudaGetSymbolAddress((void**)&ad_,  d_ad);
    cudaGetSymbolAddress((void**)&wcat, d_wcat);
    cudaGetSymbolAddress((void**)&bcat, d_bcat);
    cudaGetSymbolAddress((void**)&off,  d_off);
    cudaGetSymbolAddress((void**)&cur,  d_cur);
    cudaGetSymbolAddress((void**)&csrs, d_csrs);
    cudaGetSymbolAddress((void**)&bsum, d_bsum);

    detect_kernel<<<1, 32>>>((const int*)ei);

    // ---- CSR build (once, used by both GAT layers) ----
    cudaMemsetAsync(cur, 0, (size_t)N * sizeof(int), 0);
    hist_kernel<<<(TOT + 255) / 256, 256>>>(ei, E, N, cur);
    int nb = (N + 1023) / 1024;
    scan1_kernel<<<nb, 1024>>>(cur, off, bsum, N);
    scan23_kernel<<<(N + 255) / 256, 256>>>(off, bsum, cur, N, TOT, nb);
    scatter_kernel<<<(TOT + 255) / 256, 256>>>(ei, E, N, cur, csrs);

    int gblocks = (N + 127) / 128;

    // ---- cell encoder ----
    encoder1_kernel<<<(N * 128 + 255) / 256, 256>>>(x, ce_w1, ce_b1, t, N);
    gemm_tf32_kernel<<<gblocks, 256>>>(t, ce_w2, ce_b2, h, 0);

    // ---- two GAT layers ----
    for (int layer = 0; layer < 2; layer++) {
        const float* gw  = (const float*)d_in[layer ? 10 : 6];
        const float* gas = (const float*)d_in[layer ? 11 : 7];
        const float* gad = (const float*)d_in[layer ? 12 : 8];
        const float* gb  = (const float*)d_in[layer ? 13 : 9];

        gemm_gat_tf32_kernel<<<gblocks, 256>>>(h, gw, gas, gad, gh, as_, ad_);
        gat_gather_kernel<<<(N * 8 + 255) / 256, 256>>>(
            off, csrs, as_, ad_, gh, gb, h, N, layer == 0 ? 1 : 0);
    }

    // ---- output heads ----
    concat_kernel<<<(128 * 128 + 255) / 256, 256>>>(ed_w1, ed_b1, rp_w1, rp_b1,
                                                    wcat, bcat);
    gemm_tf32_kernel<<<gblocks, 256>>>(h, wcat, bcat, t, 1);
    heads_kernel<<<(N * 32 + 255) / 256, 256>>>(t, ed_w2, ed_b2, rp_w2, rp_b2,
                                                (float*)d_out, N);
}